// round 8
// baseline (speedup 1.0000x reference)
#include <cuda_runtime.h>
#include <cuda_bf16.h>
#include <cstdint>

// ---------------------------------------------------------------------------
// BiLSTM: B=32, T=512, D=512, H=512. out = [B,T,2H] fp32.
// Phase 1: mma.sync tf32 GEMM  xg = W_ih @ x^T (+bias)
// Phase 2: persistent recurrent scan, bf16 split mma (W0h0+W0h1+W1h0),
//          K-split x2 across 16 warps, W0 frags hoisted to registers.
// ---------------------------------------------------------------------------

#define B_  32
#define T_  512
#define D_  512
#define H_  512
#define G4  2048
#define NB  128           // persistent blocks in scan kernel
#define SH  520           // scan smem bf16 row stride (pad: conflict-free ldmatrix)

// Scratch (device globals: allocation-free rule)
__device__ float g_xg[2][T_][G4][B_];             // [dir][t][gate*H+j][b]
__device__ __nv_bfloat16 g_h0[2][2][B_][H_];      // [buf][dir][b][j] hi plane
__device__ __nv_bfloat16 g_h1[2][2][B_][H_];      // [buf][dir][b][j] lo plane
__device__ volatile unsigned g_bar;

// ---------------------------------------------------------------------------
__device__ __forceinline__ uint32_t f2tf32(float f) {
    uint32_t r;
    asm("cvt.rna.tf32.f32 %0, %1;" : "=r"(r) : "f"(f));
    return r;
}
__device__ __forceinline__ void mma_tf32(float* c, const uint32_t* a, const uint32_t* b) {
    asm volatile(
        "mma.sync.aligned.m16n8k8.row.col.f32.tf32.tf32.f32 "
        "{%0,%1,%2,%3}, {%4,%5,%6,%7}, {%8,%9}, {%0,%1,%2,%3};"
        : "+f"(c[0]), "+f"(c[1]), "+f"(c[2]), "+f"(c[3])
        : "r"(a[0]), "r"(a[1]), "r"(a[2]), "r"(a[3]), "r"(b[0]), "r"(b[1]));
}
__device__ __forceinline__ void mma_bf16(float* c, const uint32_t* a, const uint32_t* b) {
    asm volatile(
        "mma.sync.aligned.m16n8k16.row.col.f32.bf16.bf16.f32 "
        "{%0,%1,%2,%3}, {%4,%5,%6,%7}, {%8,%9}, {%0,%1,%2,%3};"
        : "+f"(c[0]), "+f"(c[1]), "+f"(c[2]), "+f"(c[3])
        : "r"(a[0]), "r"(a[1]), "r"(a[2]), "r"(a[3]), "r"(b[0]), "r"(b[1]));
}
__device__ __forceinline__ void ldmx4(uint32_t* r, uint32_t addr) {
    asm volatile("ldmatrix.sync.aligned.m8n8.x4.shared.b16 {%0,%1,%2,%3}, [%4];"
        : "=r"(r[0]), "=r"(r[1]), "=r"(r[2]), "=r"(r[3]) : "r"(addr));
}
__device__ __forceinline__ void ldmx2(uint32_t* r, uint32_t addr) {
    asm volatile("ldmatrix.sync.aligned.m8n8.x2.shared.b16 {%0,%1}, [%2];"
        : "=r"(r[0]), "=r"(r[1]) : "r"(addr));
}
__device__ __forceinline__ uint32_t smem_u32(const void* p) {
    uint32_t a;
    asm("{ .reg .u64 t; cvta.to.shared.u64 t, %1; cvt.u32.u64 %0, t; }"
        : "=r"(a) : "l"(p));
    return a;
}
__device__ __forceinline__ uint16_t bfu(__nv_bfloat16 v) {
    return __bfloat16_as_ushort(v);
}

// fast activations (MUFU EX2 based; overflow-safe) — validated R4/R6/R7
__device__ __forceinline__ float sigf(float x) {
    return __fdividef(1.f, 1.f + __expf(-x));
}
__device__ __forceinline__ float tanhfast(float x) {
    float ax = fabsf(x);
    float e  = __expf(-2.f * ax);
    float t  = __fdividef(1.f - e, 1.f + e);
    return copysignf(t, x);
}

// ---------------------------------------------------------------------------
// Phase 1: tf32 mma.sync GEMM (validated R6/R7). Unchanged.
// ---------------------------------------------------------------------------
#define SSTR 136
#define KCH  32

__global__ __launch_bounds__(256, 2) void proj_mma_kernel(
    const float* __restrict__ x,
    const float* __restrict__ Wf, const float* __restrict__ Wb,
    const float* __restrict__ bihf, const float* __restrict__ bhhf,
    const float* __restrict__ bihb, const float* __restrict__ bhhb)
{
    __shared__ __align__(16) float A_s[KCH * SSTR];
    __shared__ __align__(16) float B_s[KCH * SSTR];

    const int tid  = threadIdx.x;
    const int lane = tid & 31;
    const int wid  = tid >> 5;
    const int mw   = wid & 1;
    const int nw   = wid >> 1;

    if (blockIdx.x == 0 && blockIdx.y == 0) {
        if (tid == 0) *(unsigned*)&g_bar = 0u;
        uint4* z0 = (uint4*)&g_h0[0][0][0][0];
        uint4* z1 = (uint4*)&g_h1[0][0][0][0];
#pragma unroll
        for (int i = 0; i < 16; i++) {
            z0[tid + (i << 8)] = make_uint4(0, 0, 0, 0);
            z1[tid + (i << 8)] = make_uint4(0, 0, 0, 0);
        }
    }

    const int mtile = blockIdx.y;
    const int dir   = mtile >> 4;
    const int mg0   = (mtile & 15) * 128;
    const int t0    = blockIdx.x * 4;
    const float* W  = dir ? Wb : Wf;

    const int lrow = tid >> 1;
    const int lseg = tid & 1;
    const int bL   = lrow & 31;
    const int dtL  = lrow >> 5;
    const float* Arow = W + (size_t)(mg0 + lrow) * D_;
    const float* Brow = x + ((size_t)bL * T_ + t0 + dtL) * D_;

    float acc[4][4][4];
#pragma unroll
    for (int mi = 0; mi < 4; mi++)
#pragma unroll
        for (int ni = 0; ni < 4; ni++)
#pragma unroll
            for (int q = 0; q < 4; q++) acc[mi][ni][q] = 0.f;

    const int frag_k = lane & 3;
    const int frag_r = lane >> 2;

    for (int c = 0; c < D_ / KCH; c++) {
        const int kc = c * KCH;
#pragma unroll
        for (int it = 0; it < 4; it++) {
            int seg = it * 2 + lseg;
            int k0  = seg * 4;
            float4 av = *(const float4*)(Arow + kc + k0);
            float4 bv = *(const float4*)(Brow + kc + k0);
            A_s[(k0 + 0) * SSTR + lrow] = __uint_as_float(f2tf32(av.x));
            A_s[(k0 + 1) * SSTR + lrow] = __uint_as_float(f2tf32(av.y));
            A_s[(k0 + 2) * SSTR + lrow] = __uint_as_float(f2tf32(av.z));
            A_s[(k0 + 3) * SSTR + lrow] = __uint_as_float(f2tf32(av.w));
            B_s[(k0 + 0) * SSTR + lrow] = __uint_as_float(f2tf32(bv.x));
            B_s[(k0 + 1) * SSTR + lrow] = __uint_as_float(f2tf32(bv.y));
            B_s[(k0 + 2) * SSTR + lrow] = __uint_as_float(f2tf32(bv.z));
            B_s[(k0 + 3) * SSTR + lrow] = __uint_as_float(f2tf32(bv.w));
        }
        __syncthreads();

#pragma unroll
        for (int ks = 0; ks < KCH / 8; ks++) {
            const int kb = ks * 8 + frag_k;
            uint32_t afr[4][4], bfr[4][2];
#pragma unroll
            for (int mi = 0; mi < 4; mi++) {
                int m = mw * 64 + mi * 16 + frag_r;
                afr[mi][0] = __float_as_uint(A_s[kb * SSTR + m]);
                afr[mi][1] = __float_as_uint(A_s[kb * SSTR + m + 8]);
                afr[mi][2] = __float_as_uint(A_s[(kb + 4) * SSTR + m]);
                afr[mi][3] = __float_as_uint(A_s[(kb + 4) * SSTR + m + 8]);
            }
#pragma unroll
            for (int ni = 0; ni < 4; ni++) {
                int n = nw * 32 + ni * 8 + frag_r;
                bfr[ni][0] = __float_as_uint(B_s[kb * SSTR + n]);
                bfr[ni][1] = __float_as_uint(B_s[(kb + 4) * SSTR + n]);
            }
#pragma unroll
            for (int mi = 0; mi < 4; mi++)
#pragma unroll
                for (int ni = 0; ni < 4; ni++)
                    mma_tf32(acc[mi][ni], afr[mi], bfr[ni]);
        }
        __syncthreads();
    }

    const int t  = t0 + nw;
    const int bc = 2 * (lane & 3);
#pragma unroll
    for (int mi = 0; mi < 4; mi++) {
        int g0 = mg0 + mw * 64 + mi * 16 + frag_r;
        float bias0 = dir ? (bihb[g0] + bhhb[g0]) : (bihf[g0] + bhhf[g0]);
        float bias1 = dir ? (bihb[g0 + 8] + bhhb[g0 + 8]) : (bihf[g0 + 8] + bhhf[g0 + 8]);
#pragma unroll
        for (int ni = 0; ni < 4; ni++) {
            int b = ni * 8 + bc;
            *(float2*)&g_xg[dir][t][g0][b] =
                make_float2(acc[mi][ni][0] + bias0, acc[mi][ni][1] + bias0);
            *(float2*)&g_xg[dir][t][g0 + 8][b] =
                make_float2(acc[mi][ni][2] + bias1, acc[mi][ni][3] + bias1);
        }
    }
}

// ---------------------------------------------------------------------------
// Grid barrier (all NB blocks co-resident; fenced monotonic counter)
// ---------------------------------------------------------------------------
__device__ __forceinline__ void grid_sync(unsigned target) {
    __threadfence();
    __syncthreads();
    if (threadIdx.x == 0) {
        atomicAdd((unsigned*)&g_bar, 1u);
        while (g_bar < target) { }
        __threadfence();
    }
    __syncthreads();
}

// ---------------------------------------------------------------------------
// Phase 2: persistent scan, bf16 split mma, K-split x2, W0 in registers.
// 128 blocks = 2 dirs x 64 j-tiles(8). 512 threads = 16 warps:
//   kw = wid>>3 (K half), wm = (wid>>2)&1 (m16 half), wn = wid&3 (n8 quarter)
// Per step per block: gates[32 m', 32 b] = Whh_blk[32,512] @ h[512,32]
//   3-term: W0h0(reg A) + W0h1(reg A) + W1h0(smem A).
// Partial C per K-half summed in epilogue via smem.
// ---------------------------------------------------------------------------
#define KS_W 16            // k16-steps per warp (K half = 256)
// dynamic smem layout (bytes):
#define W0_OFF 0
#define W1_OFF 33280
#define H0_OFF 66560
#define H1_OFF 99840
#define CS_OFF 133120      // float [2][32][36]
#define HN_OFF 142336      // float [32][9]
#define SMEM_TOT 143488

__global__ __launch_bounds__(512, 1) void lstm_scan_kernel(
    const int*   __restrict__ lengths,
    const float* __restrict__ Whf,
    const float* __restrict__ Whb,
    float*       __restrict__ out)
{
    extern __shared__ __align__(16) char sm[];
    __nv_bfloat16* W0_s = (__nv_bfloat16*)(sm + W0_OFF);
    __nv_bfloat16* W1_s = (__nv_bfloat16*)(sm + W1_OFF);
    __nv_bfloat16* h0_s = (__nv_bfloat16*)(sm + H0_OFF);
    __nv_bfloat16* h1_s = (__nv_bfloat16*)(sm + H1_OFF);
    float* C_s  = (float*)(sm + CS_OFF);   // [2][32][36]
    float* hn_s = (float*)(sm + HN_OFF);   // [32][9]

    const int tid  = threadIdx.x;
    const int lane = tid & 31;
    const int wid  = tid >> 5;
    const int bx   = blockIdx.x;
    const int dir  = bx >> 6;
    const int j0   = (bx & 63) << 3;
    const float* W = dir ? Whb : Whf;

    // ---- stage W split into smem (once): row m' = gate*8+jj ----
#pragma unroll
    for (int i = 0; i < 8; i++) {
        int v = tid + i * 512;              // 0..4095
        int mrow = v >> 7;                  // 0..31
        int seg  = v & 127;                 // float4 index
        int gate = mrow >> 3, jj = mrow & 7;
        float4 wv = __ldg((const float4*)(W + (size_t)((gate << 9) + j0 + jj) * D_) + seg);
        __nv_bfloat16 h0 = __float2bfloat16_rn(wv.x);
        __nv_bfloat16 h1 = __float2bfloat16_rn(wv.y);
        __nv_bfloat16 h2 = __float2bfloat16_rn(wv.z);
        __nv_bfloat16 h3 = __float2bfloat16_rn(wv.w);
        __nv_bfloat16 l0 = __float2bfloat16_rn(wv.x - __bfloat162float(h0));
        __nv_bfloat16 l1 = __float2bfloat16_rn(wv.y - __bfloat162float(h1));
        __nv_bfloat16 l2 = __float2bfloat16_rn(wv.z - __bfloat162float(h2));
        __nv_bfloat16 l3 = __float2bfloat16_rn(wv.w - __bfloat162float(h3));
        uint32_t hA = (uint32_t)bfu(h0) | ((uint32_t)bfu(h1) << 16);
        uint32_t hB = (uint32_t)bfu(h2) | ((uint32_t)bfu(h3) << 16);
        uint32_t lA = (uint32_t)bfu(l0) | ((uint32_t)bfu(l1) << 16);
        uint32_t lB = (uint32_t)bfu(l2) | ((uint32_t)bfu(l3) << 16);
        int eoff = mrow * SH + seg * 4;
        *(uint2*)((char*)W0_s + eoff * 2) = make_uint2(hA, hB);
        *(uint2*)((char*)W1_s + eoff * 2) = make_uint2(lA, lB);
    }
    __syncthreads();

    // warp decomposition
    const int kw = wid >> 3;           // 0..1 K half
    const int wm = (wid >> 2) & 1;     // m16 half
    const int wn = wid & 3;            // n8 quarter
    const int l8 = lane & 7, sel = lane >> 3;
    const uint32_t aoff =
        (uint32_t)(((wm * 16) + ((sel & 1) ? 8 : 0) + l8) * SH + ((sel >> 1) ? 8 : 0)) * 2;
    const uint32_t boff =
        (uint32_t)(((wn * 8) + l8) * SH + ((sel & 1) ? 8 : 0)) * 2;
    const uint32_t kbase = (uint32_t)(kw * 256) * 2;    // byte offset of K half
    const uint32_t w0b = smem_u32(W0_s), w1b = smem_u32(W1_s);
    const uint32_t h0b = smem_u32(h0_s), h1b = smem_u32(h1_s);

    // ---- hoist W0 fragments (time-invariant): 16 ks x 4 regs ----
    uint32_t a0h[KS_W][4];
#pragma unroll
    for (int ks = 0; ks < KS_W; ks++)
        ldmx4(a0h[ks], w0b + aoff + kbase + ks * 32);

    // cell identity (threads 0..255): jj = tid>>5, b = tid&31
    const int jj = wid & 7;
    const int b  = lane;
    const bool is_cell = (tid < 256);
    const int len = __ldg(&lengths[b]);
    float c_reg = 0.f, h_reg = 0.f;
    int cur = 0;
    unsigned target = 0;

    for (int s = 0; s < T_; s++) {
        target += NB;
        grid_sync(target);

        // ---- stage h planes: 2048 uint4 per plane / 512 thr = 4 iters ----
        const uint4* s0 = (const uint4*)&g_h0[cur][dir][0][0];
        const uint4* s1 = (const uint4*)&g_h1[cur][dir][0][0];
#pragma unroll
        for (int i = 0; i < 4; i++) {
            int v = tid + i * 512;          // 0..2047
            int bb = v >> 6, seg = v & 63;
            int eoff = bb * SH + seg * 8;
            *(uint4*)((char*)h0_s + eoff * 2) = __ldcg(s0 + v);
            *(uint4*)((char*)h1_s + eoff * 2) = __ldcg(s1 + v);
        }

        const int t = dir ? (T_ - 1 - s) : s;

        // ---- prefetch xg (cell threads) while stage loads are in flight ----
        float xi = 0.f, xf = 0.f, xgv = 0.f, xo = 0.f;
        if (is_cell) {
            const float* xgp = &g_xg[dir][t][0][0];
            xi  = __ldg(xgp + (((0 << 9) + j0 + jj) << 5) + b);
            xf  = __ldg(xgp + (((1 << 9) + j0 + jj) << 5) + b);
            xgv = __ldg(xgp + (((2 << 9) + j0 + jj) << 5) + b);
            xo  = __ldg(xgp + (((3 << 9) + j0 + jj) << 5) + b);
        }
        __syncthreads();

        // ---- mma mainloop: 16 k16-steps, 3 terms; W0 from registers ----
        float c[4] = {0.f, 0.f, 0.f, 0.f};
#pragma unroll 8
        for (int ks = 0; ks < KS_W; ks++) {
            uint32_t koff = kbase + ks * 32;
            uint32_t a1[4], b0[2], b1[2];
            ldmx2(b0, h0b + boff + koff);
            ldmx2(b1, h1b + boff + koff);
            ldmx4(a1, w1b + aoff + koff);
            mma_bf16(c, a0h[ks], b0);
            mma_bf16(c, a0h[ks], b1);
            mma_bf16(c, a1, b0);
        }

        // ---- partial C frags -> C_s[kw][m'][b] ----
        {
            int r = lane >> 2, cp = (lane & 3) * 2;
            float* Ck = C_s + kw * 32 * 36;
            *(float2*)&Ck[(wm * 16 + r) * 36 + wn * 8 + cp]     = make_float2(c[0], c[1]);
            *(float2*)&Ck[(wm * 16 + r + 8) * 36 + wn * 8 + cp] = make_float2(c[2], c[3]);
        }
        __syncthreads();

        // ---- LSTM cell for (jj, b): sum K halves ----
        if (is_cell) {
            float ri = C_s[(0 * 8 + jj) * 36 + b] + C_s[(32 + 0 * 8 + jj) * 36 + b] + xi;
            float rf = C_s[(1 * 8 + jj) * 36 + b] + C_s[(32 + 1 * 8 + jj) * 36 + b] + xf;
            float rg = C_s[(2 * 8 + jj) * 36 + b] + C_s[(32 + 2 * 8 + jj) * 36 + b] + xgv;
            float ro = C_s[(3 * 8 + jj) * 36 + b] + C_s[(32 + 3 * 8 + jj) * 36 + b] + xo;
            float ig = sigf(ri), fg = sigf(rf);
            float gg = tanhfast(rg), og = sigf(ro);
            float cn = fg * c_reg + ig * gg;
            float hn = og * tanhfast(cn);
            if (t < len) { c_reg = cn; h_reg = hn; }
            hn_s[b * 9 + jj] = h_reg;
        }
        __syncthreads();

        // ---- out store (threads 0..255) ----
        if (is_cell) {
            int bo = tid >> 3, jo = tid & 7;
            out[((size_t)bo * T_ + t) * (2 * H_) + (dir << 9) + j0 + jo] = hn_s[bo * 9 + jo];
        }
        // ---- pack h -> global bf16 planes (threads 0..63) ----
        if (tid < 64) {
            int bb = tid >> 1, q4 = (tid & 1) * 4;
            float v0 = hn_s[bb * 9 + q4 + 0];
            float v1 = hn_s[bb * 9 + q4 + 1];
            float v2 = hn_s[bb * 9 + q4 + 2];
            float v3 = hn_s[bb * 9 + q4 + 3];
            __nv_bfloat16 p0 = __float2bfloat16_rn(v0);
            __nv_bfloat16 p1 = __float2bfloat16_rn(v1);
            __nv_bfloat16 p2 = __float2bfloat16_rn(v2);
            __nv_bfloat16 p3 = __float2bfloat16_rn(v3);
            __nv_bfloat16 q0 = __float2bfloat16_rn(v0 - __bfloat162float(p0));
            __nv_bfloat16 q1 = __float2bfloat16_rn(v1 - __bfloat162float(p1));
            __nv_bfloat16 q2 = __float2bfloat16_rn(v2 - __bfloat162float(p2));
            __nv_bfloat16 q3 = __float2bfloat16_rn(v3 - __bfloat162float(p3));
            uint2 hw = make_uint2((uint32_t)bfu(p0) | ((uint32_t)bfu(p1) << 16),
                                  (uint32_t)bfu(p2) | ((uint32_t)bfu(p3) << 16));
            uint2 lw = make_uint2((uint32_t)bfu(q0) | ((uint32_t)bfu(q1) << 16),
                                  (uint32_t)bfu(q2) | ((uint32_t)bfu(q3) << 16));
            __stcg((uint2*)&g_h0[cur ^ 1][dir][bb][j0 + q4], hw);
            __stcg((uint2*)&g_h1[cur ^ 1][dir][bb][j0 + q4], lw);
        }
        cur ^= 1;
    }
}

// ---------------------------------------------------------------------------
extern "C" void kernel_launch(void* const* d_in, const int* in_sizes, int n_in,
                              void* d_out, int out_size)
{
    const float* x      = (const float*)d_in[0];
    const int*   lens   = (const int*)  d_in[1];
    const float* Wihf   = (const float*)d_in[2];
    const float* Whhf   = (const float*)d_in[3];
    const float* bihf   = (const float*)d_in[4];
    const float* bhhf   = (const float*)d_in[5];
    const float* Wihb   = (const float*)d_in[6];
    const float* Whhb   = (const float*)d_in[7];
    const float* bihb   = (const float*)d_in[8];
    const float* bhhb   = (const float*)d_in[9];
    float* out = (float*)d_out;

    cudaFuncSetAttribute(lstm_scan_kernel,
                         cudaFuncAttributeMaxDynamicSharedMemorySize, SMEM_TOT);

    dim3 pg(T_ / 4, 32);
    proj_mma_kernel<<<pg, 256>>>(x, Wihf, Wihb, bihf, bhhf, bihb, bhhb);

    lstm_scan_kernel<<<NB, 512, SMEM_TOT>>>(lens, Whhf, Whhb, out);
}

// round 9
// speedup vs baseline: 1.1477x; 1.1477x over previous
#include <cuda_runtime.h>
#include <cuda_fp16.h>
#include <cstdint>

// ---------------------------------------------------------------------------
// BiLSTM: B=32, T=512, D=512, H=512. out = [B,T,2H] fp32.
// Phase 1: mma.sync tf32 GEMM  xg = W_ih @ x^T (+bias)
// Phase 2: persistent recurrent scan, fp16 split mma (W0h + W1h*2^-11),
//          K-split x2, W0 in registers, per-warp cp.async h staging,
//          per-direction grid barriers.
// ---------------------------------------------------------------------------

#define B_  32
#define T_  512
#define D_  512
#define H_  512
#define G4  2048
#define NBD 64            // blocks per direction in scan
#define SH  520           // W smem fp16 row stride
#define HSTR 264          // private h slice row stride (fp16 elems)

// Scratch (device globals: allocation-free rule)
__device__ float g_xg[2][T_][G4][B_];        // [dir][t][gate*H+j][b]
__device__ __half g_h[2][2][B_][H_];         // [buf][dir][b][j] fp16
__device__ unsigned g_bar2[2];               // per-dir barrier counters

// ---------------------------------------------------------------------------
__device__ __forceinline__ uint32_t f2tf32(float f) {
    uint32_t r;
    asm("cvt.rna.tf32.f32 %0, %1;" : "=r"(r) : "f"(f));
    return r;
}
__device__ __forceinline__ void mma_tf32(float* c, const uint32_t* a, const uint32_t* b) {
    asm volatile(
        "mma.sync.aligned.m16n8k8.row.col.f32.tf32.tf32.f32 "
        "{%0,%1,%2,%3}, {%4,%5,%6,%7}, {%8,%9}, {%0,%1,%2,%3};"
        : "+f"(c[0]), "+f"(c[1]), "+f"(c[2]), "+f"(c[3])
        : "r"(a[0]), "r"(a[1]), "r"(a[2]), "r"(a[3]), "r"(b[0]), "r"(b[1]));
}
__device__ __forceinline__ void mma_f16(float* c, const uint32_t* a, const uint32_t* b) {
    asm volatile(
        "mma.sync.aligned.m16n8k16.row.col.f32.f16.f16.f32 "
        "{%0,%1,%2,%3}, {%4,%5,%6,%7}, {%8,%9}, {%0,%1,%2,%3};"
        : "+f"(c[0]), "+f"(c[1]), "+f"(c[2]), "+f"(c[3])
        : "r"(a[0]), "r"(a[1]), "r"(a[2]), "r"(a[3]), "r"(b[0]), "r"(b[1]));
}
__device__ __forceinline__ void ldmx4(uint32_t* r, uint32_t addr) {
    asm volatile("ldmatrix.sync.aligned.m8n8.x4.shared.b16 {%0,%1,%2,%3}, [%4];"
        : "=r"(r[0]), "=r"(r[1]), "=r"(r[2]), "=r"(r[3]) : "r"(addr));
}
__device__ __forceinline__ void ldmx2(uint32_t* r, uint32_t addr) {
    asm volatile("ldmatrix.sync.aligned.m8n8.x2.shared.b16 {%0,%1}, [%2];"
        : "=r"(r[0]), "=r"(r[1]) : "r"(addr));
}
__device__ __forceinline__ uint32_t smem_u32(const void* p) {
    uint32_t a;
    asm("{ .reg .u64 t; cvta.to.shared.u64 t, %1; cvt.u32.u64 %0, t; }"
        : "=r"(a) : "l"(p));
    return a;
}
__device__ __forceinline__ void cp_async16(uint32_t dst, const void* src) {
    asm volatile("cp.async.cg.shared.global [%0], [%1], 16;" :: "r"(dst), "l"(src));
}
__device__ __forceinline__ uint16_t hfu(__half v) { return __half_as_ushort(v); }

// fast activations (validated R4/R6/R7/R8)
__device__ __forceinline__ float sigf(float x) {
    return __fdividef(1.f, 1.f + __expf(-x));
}
__device__ __forceinline__ float tanhfast(float x) {
    float ax = fabsf(x);
    float e  = __expf(-2.f * ax);
    float t  = __fdividef(1.f - e, 1.f + e);
    return copysignf(t, x);
}

// ---------------------------------------------------------------------------
// Phase 1: tf32 mma.sync GEMM (validated R6/R7/R8). Unchanged except init.
// ---------------------------------------------------------------------------
#define SSTR 136
#define KCH  32

__global__ __launch_bounds__(256, 2) void proj_mma_kernel(
    const float* __restrict__ x,
    const float* __restrict__ Wf, const float* __restrict__ Wb,
    const float* __restrict__ bihf, const float* __restrict__ bhhf,
    const float* __restrict__ bihb, const float* __restrict__ bhhb)
{
    __shared__ __align__(16) float A_s[KCH * SSTR];
    __shared__ __align__(16) float B_s[KCH * SSTR];

    const int tid  = threadIdx.x;
    const int lane = tid & 31;
    const int wid  = tid >> 5;
    const int mw   = wid & 1;
    const int nw   = wid >> 1;

    if (blockIdx.x == 0 && blockIdx.y == 0) {
        if (tid == 0) { g_bar2[0] = 0u; g_bar2[1] = 0u; }
        uint4* z = (uint4*)&g_h[0][0][0][0];     // 8192 uint4 (both bufs/dirs)
#pragma unroll
        for (int i = 0; i < 32; i++)
            z[tid + (i << 8)] = make_uint4(0, 0, 0, 0);
    }

    const int mtile = blockIdx.y;
    const int dir   = mtile >> 4;
    const int mg0   = (mtile & 15) * 128;
    const int t0    = blockIdx.x * 4;
    const float* W  = dir ? Wb : Wf;

    const int lrow = tid >> 1;
    const int lseg = tid & 1;
    const int bL   = lrow & 31;
    const int dtL  = lrow >> 5;
    const float* Arow = W + (size_t)(mg0 + lrow) * D_;
    const float* Brow = x + ((size_t)bL * T_ + t0 + dtL) * D_;

    float acc[4][4][4];
#pragma unroll
    for (int mi = 0; mi < 4; mi++)
#pragma unroll
        for (int ni = 0; ni < 4; ni++)
#pragma unroll
            for (int q = 0; q < 4; q++) acc[mi][ni][q] = 0.f;

    const int frag_k = lane & 3;
    const int frag_r = lane >> 2;

    for (int c = 0; c < D_ / KCH; c++) {
        const int kc = c * KCH;
#pragma unroll
        for (int it = 0; it < 4; it++) {
            int seg = it * 2 + lseg;
            int k0  = seg * 4;
            float4 av = *(const float4*)(Arow + kc + k0);
            float4 bv = *(const float4*)(Brow + kc + k0);
            A_s[(k0 + 0) * SSTR + lrow] = __uint_as_float(f2tf32(av.x));
            A_s[(k0 + 1) * SSTR + lrow] = __uint_as_float(f2tf32(av.y));
            A_s[(k0 + 2) * SSTR + lrow] = __uint_as_float(f2tf32(av.z));
            A_s[(k0 + 3) * SSTR + lrow] = __uint_as_float(f2tf32(av.w));
            B_s[(k0 + 0) * SSTR + lrow] = __uint_as_float(f2tf32(bv.x));
            B_s[(k0 + 1) * SSTR + lrow] = __uint_as_float(f2tf32(bv.y));
            B_s[(k0 + 2) * SSTR + lrow] = __uint_as_float(f2tf32(bv.z));
            B_s[(k0 + 3) * SSTR + lrow] = __uint_as_float(f2tf32(bv.w));
        }
        __syncthreads();

#pragma unroll
        for (int ks = 0; ks < KCH / 8; ks++) {
            const int kb = ks * 8 + frag_k;
            uint32_t afr[4][4], bfr[4][2];
#pragma unroll
            for (int mi = 0; mi < 4; mi++) {
                int m = mw * 64 + mi * 16 + frag_r;
                afr[mi][0] = __float_as_uint(A_s[kb * SSTR + m]);
                afr[mi][1] = __float_as_uint(A_s[kb * SSTR + m + 8]);
                afr[mi][2] = __float_as_uint(A_s[(kb + 4) * SSTR + m]);
                afr[mi][3] = __float_as_uint(A_s[(kb + 4) * SSTR + m + 8]);
            }
#pragma unroll
            for (int ni = 0; ni < 4; ni++) {
                int n = nw * 32 + ni * 8 + frag_r;
                bfr[ni][0] = __float_as_uint(B_s[kb * SSTR + n]);
                bfr[ni][1] = __float_as_uint(B_s[(kb + 4) * SSTR + n]);
            }
#pragma unroll
            for (int mi = 0; mi < 4; mi++)
#pragma unroll
                for (int ni = 0; ni < 4; ni++)
                    mma_tf32(acc[mi][ni], afr[mi], bfr[ni]);
        }
        __syncthreads();
    }

    const int t  = t0 + nw;
    const int bc = 2 * (lane & 3);
#pragma unroll
    for (int mi = 0; mi < 4; mi++) {
        int g0 = mg0 + mw * 64 + mi * 16 + frag_r;
        float bias0 = dir ? (bihb[g0] + bhhb[g0]) : (bihf[g0] + bhhf[g0]);
        float bias1 = dir ? (bihb[g0 + 8] + bhhb[g0 + 8]) : (bihf[g0 + 8] + bhhf[g0 + 8]);
#pragma unroll
        for (int ni = 0; ni < 4; ni++) {
            int b = ni * 8 + bc;
            *(float2*)&g_xg[dir][t][g0][b] =
                make_float2(acc[mi][ni][0] + bias0, acc[mi][ni][1] + bias0);
            *(float2*)&g_xg[dir][t][g0 + 8][b] =
                make_float2(acc[mi][ni][2] + bias1, acc[mi][ni][3] + bias1);
        }
    }
}

// ---------------------------------------------------------------------------
// Per-dir grid barrier (proven fence+atomic pattern, 64 arrivals)
// ---------------------------------------------------------------------------
__device__ __forceinline__ void grid_sync_dir(unsigned* ctr, unsigned target) {
    __threadfence();
    __syncthreads();
    if (threadIdx.x == 0) {
        atomicAdd(ctr, 1u);
        while (*(volatile unsigned*)ctr < target) { }
        __threadfence();
    }
    __syncthreads();
}

// ---------------------------------------------------------------------------
// Phase 2: persistent scan. 128 blocks = 2 dirs x 64 j-tiles(8).
// 512 threads = 16 warps: kw = wid>>3, wm = (wid>>2)&1, wn = wid&3.
// gates[32 m', 32 b] = Whh_blk[32,512] @ h[512,32]
//   2-term fp16: W0 h (reg A) + W1 h (smem A, x2048-scaled, rescaled at C).
// Each warp cp.asyncs its private 8x256 h slice (per-warp wait, no block sync).
// ---------------------------------------------------------------------------
#define KS_W 16
#define INV2048 (1.0f / 2048.0f)
// dynamic smem (bytes):
#define W0_OFF 0
#define W1_OFF 33280
#define HP_OFF 66560        // 16 warp regions x 8*HSTR fp16 (4224 B each)
#define CS_OFF 134144       // float [2][32][36]
#define HN_OFF 143360       // float [32][9]
#define SMEM_TOT 144512

__global__ __launch_bounds__(512, 1) void lstm_scan_kernel(
    const int*   __restrict__ lengths,
    const float* __restrict__ Whf,
    const float* __restrict__ Whb,
    float*       __restrict__ out)
{
    extern __shared__ __align__(16) char sm[];
    __half* W0_s = (__half*)(sm + W0_OFF);
    __half* W1_s = (__half*)(sm + W1_OFF);
    float*  C_s  = (float*)(sm + CS_OFF);   // [2][32][36]
    float*  hn_s = (float*)(sm + HN_OFF);   // [32][9]

    const int tid  = threadIdx.x;
    const int lane = tid & 31;
    const int wid  = tid >> 5;
    const int bx   = blockIdx.x;
    const int dir  = bx >> 6;
    const int j0   = (bx & 63) << 3;
    const float* W = dir ? Whb : Whf;
    unsigned* bar  = &g_bar2[dir];

    // ---- stage W fp16 split into smem (once): row m' = gate*8+jj ----
#pragma unroll
    for (int i = 0; i < 8; i++) {
        int v = tid + i * 512;              // 0..4095
        int mrow = v >> 7;
        int seg  = v & 127;
        int gate = mrow >> 3, jj = mrow & 7;
        float4 wv = __ldg((const float4*)(W + (size_t)((gate << 9) + j0 + jj) * D_) + seg);
        __half p0 = __float2half_rn(wv.x);
        __half p1 = __float2half_rn(wv.y);
        __half p2 = __float2half_rn(wv.z);
        __half p3 = __float2half_rn(wv.w);
        __half q0 = __float2half_rn((wv.x - __half2float(p0)) * 2048.f);
        __half q1 = __float2half_rn((wv.y - __half2float(p1)) * 2048.f);
        __half q2 = __float2half_rn((wv.z - __half2float(p2)) * 2048.f);
        __half q3 = __float2half_rn((wv.w - __half2float(p3)) * 2048.f);
        uint32_t hA = (uint32_t)hfu(p0) | ((uint32_t)hfu(p1) << 16);
        uint32_t hB = (uint32_t)hfu(p2) | ((uint32_t)hfu(p3) << 16);
        uint32_t lA = (uint32_t)hfu(q0) | ((uint32_t)hfu(q1) << 16);
        uint32_t lB = (uint32_t)hfu(q2) | ((uint32_t)hfu(q3) << 16);
        int eoff = mrow * SH + seg * 4;
        *(uint2*)((char*)W0_s + eoff * 2) = make_uint2(hA, hB);
        *(uint2*)((char*)W1_s + eoff * 2) = make_uint2(lA, lB);
    }
    __syncthreads();

    // warp decomposition
    const int kw = wid >> 3;
    const int wm = (wid >> 2) & 1;
    const int wn = wid & 3;
    const int l8 = lane & 7, sel = lane >> 3;
    const uint32_t aoff =
        (uint32_t)(((wm * 16) + ((sel & 1) ? 8 : 0) + l8) * SH + ((sel >> 1) ? 8 : 0)) * 2;
    const uint32_t kbase = (uint32_t)(kw * 256) * 2;
    const uint32_t w0b = smem_u32(W0_s), w1b = smem_u32(W1_s);
    const uint32_t hreg = smem_u32(sm + HP_OFF) + (uint32_t)wid * (8 * HSTR * 2);
    const uint32_t boff = hreg + (uint32_t)(l8 * HSTR + ((sel & 1) ? 8 : 0)) * 2;

    // ---- hoist W0 fragments (time-invariant) ----
    uint32_t a0h[KS_W][4];
#pragma unroll
    for (int ks = 0; ks < KS_W; ks++)
        ldmx4(a0h[ks], w0b + aoff + kbase + ks * 32);

    // cell identity (threads 0..255)
    const int jj = wid & 7;
    const int b  = lane;
    const bool is_cell = (tid < 256);
    const int len = __ldg(&lengths[b]);
    float c_reg = 0.f, h_reg = 0.f;
    int cur = 0;
    unsigned target = 0;

    for (int s = 0; s < T_; s++) {
        const int t = dir ? (T_ - 1 - s) : s;

        // ---- prefetch xg BEFORE barrier (no cross-block dependency) ----
        float xi = 0.f, xf = 0.f, xgv = 0.f, xo = 0.f;
        if (is_cell) {
            const float* xgp = &g_xg[dir][t][0][0];
            xi  = __ldg(xgp + (((0 << 9) + j0 + jj) << 5) + b);
            xf  = __ldg(xgp + (((1 << 9) + j0 + jj) << 5) + b);
            xgv = __ldg(xgp + (((2 << 9) + j0 + jj) << 5) + b);
            xo  = __ldg(xgp + (((3 << 9) + j0 + jj) << 5) + b);
        }

        target += NBD;
        grid_sync_dir(bar, target);

        // ---- per-warp private h slice: rows b = wn*8..wn*8+7, k-half kw ----
#pragma unroll
        for (int i = 0; i < 8; i++) {
            const void* src = (const char*)&g_h[cur][dir][wn * 8 + i][kw * 256] + lane * 16;
            cp_async16(hreg + (uint32_t)i * (HSTR * 2) + (uint32_t)lane * 16, src);
        }
        asm volatile("cp.async.commit_group;");
        asm volatile("cp.async.wait_group 0;" ::: "memory");
        __syncwarp();

        // ---- mma mainloop: 16 k16-steps, 2 terms; W0 from registers ----
        float c0[4] = {0.f, 0.f, 0.f, 0.f};
        float c1[4] = {0.f, 0.f, 0.f, 0.f};
#pragma unroll
        for (int ks = 0; ks < KS_W; ks++) {
            uint32_t b0[2], a1f[4];
            ldmx2(b0, boff + ks * 32);
            ldmx4(a1f, w1b + aoff + kbase + ks * 32);
            mma_f16(c0, a0h[ks], b0);
            mma_f16(c1, a1f, b0);
        }

        // ---- partial C (rescale W1 term) -> C_s[kw][m'][b] ----
        {
            int r = lane >> 2, cp2 = (lane & 3) * 2;
            float* Ck = C_s + kw * 32 * 36;
            *(float2*)&Ck[(wm * 16 + r) * 36 + wn * 8 + cp2] =
                make_float2(c0[0] + c1[0] * INV2048, c0[1] + c1[1] * INV2048);
            *(float2*)&Ck[(wm * 16 + r + 8) * 36 + wn * 8 + cp2] =
                make_float2(c0[2] + c1[2] * INV2048, c0[3] + c1[3] * INV2048);
        }
        __syncthreads();

        // ---- LSTM cell for (jj, b): sum K halves ----
        if (is_cell) {
            float ri = C_s[(0 * 8 + jj) * 36 + b] + C_s[(32 + 0 * 8 + jj) * 36 + b] + xi;
            float rf = C_s[(1 * 8 + jj) * 36 + b] + C_s[(32 + 1 * 8 + jj) * 36 + b] + xf;
            float rg = C_s[(2 * 8 + jj) * 36 + b] + C_s[(32 + 2 * 8 + jj) * 36 + b] + xgv;
            float ro = C_s[(3 * 8 + jj) * 36 + b] + C_s[(32 + 3 * 8 + jj) * 36 + b] + xo;
            float ig = sigf(ri), fg = sigf(rf);
            float gg = tanhfast(rg), og = sigf(ro);
            float cn = fg * c_reg + ig * gg;
            float hn = og * tanhfast(cn);
            if (t < len) { c_reg = cn; h_reg = hn; }
            hn_s[b * 9 + jj] = h_reg;
        }
        __syncthreads();

        // ---- out store (threads 0..255) ----
        if (is_cell) {
            int bo = tid >> 3, jo = tid & 7;
            out[((size_t)bo * T_ + t) * (2 * H_) + (dir << 9) + j0 + jo] = hn_s[bo * 9 + jo];
        }
        // ---- pack h -> global fp16 (threads 0..31: one uint4 per batch) ----
        if (tid < 32) {
            int bb = tid;
            uint32_t p[4];
#pragma unroll
            for (int q = 0; q < 4; q++) {
                __half ha = __float2half_rn(hn_s[bb * 9 + 2 * q]);
                __half hb = __float2half_rn(hn_s[bb * 9 + 2 * q + 1]);
                p[q] = (uint32_t)hfu(ha) | ((uint32_t)hfu(hb) << 16);
            }
            __stcg((uint4*)&g_h[cur ^ 1][dir][bb][j0], make_uint4(p[0], p[1], p[2], p[3]));
        }
        cur ^= 1;
    }
}

// ---------------------------------------------------------------------------
extern "C" void kernel_launch(void* const* d_in, const int* in_sizes, int n_in,
                              void* d_out, int out_size)
{
    const float* x      = (const float*)d_in[0];
    const int*   lens   = (const int*)  d_in[1];
    const float* Wihf   = (const float*)d_in[2];
    const float* Whhf   = (const float*)d_in[3];
    const float* bihf   = (const float*)d_in[4];
    const float* bhhf   = (const float*)d_in[5];
    const float* Wihb   = (const float*)d_in[6];
    const float* Whhb   = (const float*)d_in[7];
    const float* bihb   = (const float*)d_in[8];
    const float* bhhb   = (const float*)d_in[9];
    float* out = (float*)d_out;

    cudaFuncSetAttribute(lstm_scan_kernel,
                         cudaFuncAttributeMaxDynamicSharedMemorySize, SMEM_TOT);

    dim3 pg(T_ / 4, 32);
    proj_mma_kernel<<<pg, 256>>>(x, Wihf, Wihb, bihf, bhhf, bihb, bhhb);

    lstm_scan_kernel<<<2 * NBD, 512, SMEM_TOT>>>(lens, Whhf, Whhb, out);
}